// round 2
// baseline (speedup 1.0000x reference)
#include <cuda_runtime.h>
#include <math.h>

// Problem constants
#define Bb 16
#define Nn 128
#define DZ 128
#define DS 256
#define Hh 8
#define HDIM 32
#define BI (Bb*Nn)               // 2048 (b,i) pairs
#define INV_SCALE 0.17677669529663687f   // 1/sqrt(32)
#define LN_EPS 1e-5f
#define ZP 132                   // padded z-tile row stride (floats), 16B-aligned, conflict-free both ways

// ---------------- scratch (no allocations allowed) ----------------
__device__ float g_SN  [BI*DS];        // layernormed s_query
__device__ float g_Q   [BI*DS];        // q = sn @ wq^T + bq
__device__ float g_QKG [BI*Hh*DZ];     // qk[h,d]*gz[d]/scale
__device__ float g_CQ  [BI*Hh];        // per-head score constant
__device__ float g_CTX [BI*Hh*DZ];     // layernormed attention context
__device__ float g_OUTS[BI*DS];        // wv_h @ ctx + bv
__device__ float g_wkb [DS];           // wk[r,:]·bz + bk[r]
__device__ float g_Wk2 [Hh*DZ*HDIM];   // folded (wk*gz/scale) transposed: [o=h*128+d][e]

// ---------------- s_query layernorm ----------------
__global__ void ln_s_kernel(const float* __restrict__ s, const float* __restrict__ gs,
                            const float* __restrict__ bs) {
    int bi = blockIdx.x;
    int t  = threadIdx.x;
    float x = s[(size_t)bi*DS + t];
    float sm = x, sq = x*x;
    #pragma unroll
    for (int o = 16; o > 0; o >>= 1) {
        sm += __shfl_xor_sync(0xffffffffu, sm, o);
        sq += __shfl_xor_sync(0xffffffffu, sq, o);
    }
    __shared__ float ps[8], pq[8], mv[2];
    int w = t >> 5, l = t & 31;
    if (l == 0) { ps[w] = sm; pq[w] = sq; }
    __syncthreads();
    if (t == 0) {
        float a = 0.f, b2 = 0.f;
        #pragma unroll
        for (int k = 0; k < 8; k++) { a += ps[k]; b2 += pq[k]; }
        float m = a * (1.0f/DS);
        mv[0] = m;
        mv[1] = rsqrtf(b2 * (1.0f/DS) - m*m + LN_EPS);
    }
    __syncthreads();
    g_SN[(size_t)bi*DS + t] = (x - mv[0]) * mv[1] * gs[t] + bs[t];
}

// ---------------- weight prep ----------------
__global__ void prep_wkb_kernel(const float* __restrict__ wk, const float* __restrict__ bk,
                                const float* __restrict__ bz) {
    int r = threadIdx.x;                      // 0..255
    float acc = 0.f;
    for (int d = 0; d < DZ; d++) acc += wk[(size_t)r*DZ + d] * bz[d];
    g_wkb[r] = acc + bk[r];
}

__global__ void prep_wk2_kernel(const float* __restrict__ wk, const float* __restrict__ gz) {
    int idx = blockIdx.x * 256 + threadIdx.x; // 0..32767
    int o = idx >> 5, e = idx & 31;
    int h = o >> 7,  d = o & 127;
    g_Wk2[idx] = wk[(size_t)(h*HDIM + e)*DZ + d] * gz[d] * INV_SCALE;
}

// CQ[bi,h] = invscale * (qk·bz + q·bk) = invscale * sum_e Q[bi,h*32+e]*wkb[h*32+e]
__global__ void cq_kernel() {
    int idx = blockIdx.x * 256 + threadIdx.x; // 0..16383
    int bi = idx >> 3, h = idx & 7;
    float acc = 0.f;
    #pragma unroll
    for (int e = 0; e < HDIM; e++)
        acc += g_Q[(size_t)bi*DS + h*HDIM + e] * g_wkb[h*HDIM + e];
    g_CQ[idx] = acc * INV_SCALE;
}

// ---------------- generic tiled fp32 GEMM: C[r,o] = sum_k A[r, abase+k]*B[o,k] + bias[o] ----------------
// abase = (colblock_start / head_cols) * ahs  (for block-diagonal per-head projections)
__global__ void gemm_bt_kernel(const float* __restrict__ A, int lda,
                               const float* __restrict__ B, int ldb,
                               const float* __restrict__ bias,
                               float* __restrict__ C, int ldc,
                               int Kb, int head_cols, int ahs) {
    __shared__ float As[128*33];
    __shared__ float Bs[32*36];
    int t  = threadIdx.x;
    int r0 = blockIdx.y * 128, c0 = blockIdx.x * 32;
    int abase = (c0 / head_cols) * ahs;
    int rt = t >> 3, ct = t & 7;
    float4 acc[4];
    #pragma unroll
    for (int q = 0; q < 4; q++) acc[q] = make_float4(0.f, 0.f, 0.f, 0.f);

    for (int kc = 0; kc < Kb; kc += 32) {
        #pragma unroll
        for (int i = 0; i < 16; i++) {
            int idx = t + i*256;
            int row = idx >> 5, kk = idx & 31;
            As[row*33 + kk] = A[(size_t)(r0 + row)*lda + abase + kc + kk];
        }
        // B tile: 32 rows x 32 k = 256 float4 loads, exactly one per thread
        {
            int o = t >> 3, kg = t & 7;
            float4 v = *reinterpret_cast<const float4*>(&B[(size_t)(c0 + o)*ldb + kc + kg*4]);
            Bs[(kg*4+0)*36 + o] = v.x;
            Bs[(kg*4+1)*36 + o] = v.y;
            Bs[(kg*4+2)*36 + o] = v.z;
            Bs[(kg*4+3)*36 + o] = v.w;
        }
        __syncthreads();
        #pragma unroll
        for (int kk = 0; kk < 32; kk++) {
            float4 b4 = *reinterpret_cast<const float4*>(&Bs[kk*36 + ct*4]);
            #pragma unroll
            for (int q = 0; q < 4; q++) {
                float a = As[(rt*4+q)*33 + kk];
                acc[q].x += a*b4.x; acc[q].y += a*b4.y;
                acc[q].z += a*b4.z; acc[q].w += a*b4.w;
            }
        }
        __syncthreads();
    }
    float4 bv4 = make_float4(0.f, 0.f, 0.f, 0.f);
    if (bias) bv4 = *reinterpret_cast<const float4*>(&bias[c0 + ct*4]);
    #pragma unroll
    for (int q = 0; q < 4; q++) {
        float4 o4 = acc[q];
        o4.x += bv4.x; o4.y += bv4.y; o4.z += bv4.z; o4.w += bv4.w;
        *reinterpret_cast<float4*>(&C[(size_t)(r0 + rt*4 + q)*ldc + c0 + ct*4]) = o4;
    }
}

// ---------------- fused edge-LN + attention kernel: one CTA per (b,i) ----------------
// SMEM layout (floats): zt[128*ZP] | qkg[1024] | sc[1024] | pA[1024] | pB[1024] | m[128] | r[128] | A[8] | cq[8] | sh[8]
#define ATTN_SMEM_FLOATS (128*ZP + 1024*4 + 128*2 + 24)

__global__ void attn_kernel(const float* __restrict__ z, const int* __restrict__ mask,
                            const float* __restrict__ gz, const float* __restrict__ bz) {
    extern __shared__ float smem[];
    float* zt  = smem;
    float* qkg = zt  + 128*ZP;
    float* sc  = qkg + 1024;
    float* pA  = sc  + 1024;
    float* pB  = pA  + 1024;
    float* mj  = pB  + 1024;
    float* rj  = mj  + 128;
    float* Ah  = rj  + 128;
    float* cqh = Ah  + 8;
    float* sh  = cqh + 8;

    int bi = blockIdx.x;
    int b  = bi >> 7;
    int t  = threadIdx.x, w = t >> 5, l = t & 31;

    // load per-(b,i) qkg vectors and score constants
    {
        float4 v = *reinterpret_cast<const float4*>(&g_QKG[(size_t)bi*1024 + t*4]);
        *reinterpret_cast<float4*>(&qkg[t*4]) = v;
    }
    if (t < 8) cqh[t] = g_CQ[(size_t)bi*8 + t];

    // load z tile (raw) + per-row mean / rstd. warp w handles rows {w, w+8, ..., w+120}
    const float* zb = z + (size_t)bi * 128 * 128;
    for (int it = 0; it < 16; it++) {
        int j = w + it*8;
        float v0 = zb[j*128 + l];
        float v1 = zb[j*128 + l + 32];
        float v2 = zb[j*128 + l + 64];
        float v3 = zb[j*128 + l + 96];
        zt[j*ZP + l]      = v0;
        zt[j*ZP + l + 32] = v1;
        zt[j*ZP + l + 64] = v2;
        zt[j*ZP + l + 96] = v3;
        float s  = v0 + v1 + v2 + v3;
        float sq = v0*v0 + v1*v1 + v2*v2 + v3*v3;
        #pragma unroll
        for (int o = 16; o > 0; o >>= 1) {
            s  += __shfl_xor_sync(0xffffffffu, s,  o);
            sq += __shfl_xor_sync(0xffffffffu, sq, o);
        }
        if (l == 0) {
            float m = s * (1.0f/128.0f);
            mj[j] = m;
            rj[j] = rsqrtf(sq * (1.0f/128.0f) - m*m + LN_EPS);
        }
    }
    __syncthreads();

    // A[h] = sum_d qkg[h,d]   (warp w reduces head w)
    {
        float4 v = *reinterpret_cast<float4*>(&qkg[w*128 + l*4]);
        float s = v.x + v.y + v.z + v.w;
        #pragma unroll
        for (int o = 16; o > 0; o >>= 1) s += __shfl_xor_sync(0xffffffffu, s, o);
        if (l == 0) Ah[w] = s;
    }
    __syncthreads();

    // scores: thread t handles j in {jb, jb+64}, heads {h0, h0+1}
    {
        int jb = t & 63;
        int h0 = (t >> 6) * 2;
        float a00 = 0.f, a01 = 0.f, a10 = 0.f, a11 = 0.f;
        #pragma unroll 8
        for (int d4 = 0; d4 < 32; d4++) {
            float4 q0 = *reinterpret_cast<float4*>(&qkg[h0*128 + d4*4]);
            float4 q1 = *reinterpret_cast<float4*>(&qkg[(h0+1)*128 + d4*4]);
            float4 zA = *reinterpret_cast<float4*>(&zt[jb*ZP + d4*4]);
            float4 zB = *reinterpret_cast<float4*>(&zt[(jb+64)*ZP + d4*4]);
            a00 += q0.x*zA.x + q0.y*zA.y + q0.z*zA.z + q0.w*zA.w;
            a01 += q0.x*zB.x + q0.y*zB.y + q0.z*zB.z + q0.w*zB.w;
            a10 += q1.x*zA.x + q1.y*zA.y + q1.z*zA.z + q1.w*zA.w;
            a11 += q1.x*zB.x + q1.y*zB.y + q1.z*zB.z + q1.w*zB.w;
        }
        int jA = jb, jB = jb + 64;
        bool okA = mask[b*128 + jA] != 0;
        bool okB = mask[b*128 + jB] != 0;
        float rA = rj[jA], rB = rj[jB], mA = mj[jA], mB = mj[jB];
        float A0 = Ah[h0], A1 = Ah[h0+1], C0 = cqh[h0], C1 = cqh[h0+1];
        float s00 = rA*(a00 - mA*A0) + C0;
        float s01 = rB*(a01 - mB*A0) + C0;
        float s10 = rA*(a10 - mA*A1) + C1;
        float s11 = rB*(a11 - mB*A1) + C1;
        sc[h0*128 + jA]     = okA ? s00 : -3.0e38f;
        sc[h0*128 + jB]     = okB ? s01 : -3.0e38f;
        sc[(h0+1)*128 + jA] = okA ? s10 : -3.0e38f;
        sc[(h0+1)*128 + jB] = okB ? s11 : -3.0e38f;
    }
    __syncthreads();

    // softmax per head (warp w = head w); sc becomes aw = attn*r; sh[h] = sum_j aw*m
    {
        int h = w;
        float v0 = sc[h*128 + l],      v1 = sc[h*128 + l + 32];
        float v2 = sc[h*128 + l + 64], v3 = sc[h*128 + l + 96];
        float mx = fmaxf(fmaxf(v0, v1), fmaxf(v2, v3));
        #pragma unroll
        for (int o = 16; o > 0; o >>= 1) mx = fmaxf(mx, __shfl_xor_sync(0xffffffffu, mx, o));
        float e0 = expf(v0 - mx), e1 = expf(v1 - mx), e2 = expf(v2 - mx), e3 = expf(v3 - mx);
        float s = e0 + e1 + e2 + e3;
        #pragma unroll
        for (int o = 16; o > 0; o >>= 1) s += __shfl_xor_sync(0xffffffffu, s, o);
        float inv = 1.0f / s;
        float w0 = e0*inv*rj[l],      w1 = e1*inv*rj[l+32];
        float w2 = e2*inv*rj[l+64],   w3 = e3*inv*rj[l+96];
        sc[h*128 + l]      = w0;
        sc[h*128 + l + 32] = w1;
        sc[h*128 + l + 64] = w2;
        sc[h*128 + l + 96] = w3;
        float sm = w0*mj[l] + w1*mj[l+32] + w2*mj[l+64] + w3*mj[l+96];
        #pragma unroll
        for (int o = 16; o > 0; o >>= 1) sm += __shfl_xor_sync(0xffffffffu, sm, o);
        if (l == 0) sh[h] = sm;
    }
    __syncthreads();

    // ctx partials: warp -> (head pair, j half); lane owns d4 = 4*l..4*l+3
    {
        int hp = w & 3, jh = w >> 2;
        int h0 = hp * 2;
        float4 acc0 = make_float4(0.f,0.f,0.f,0.f);
        float4 acc1 = make_float4(0.f,0.f,0.f,0.f);
        int j0 = jh * 64;
        #pragma unroll 4
        for (int jj = 0; jj < 64; jj++) {
            int j = j0 + jj;
            float w0 = sc[h0*128 + j];
            float w1 = sc[(h0+1)*128 + j];
            float4 zv = *reinterpret_cast<float4*>(&zt[j*ZP + l*4]);
            acc0.x += w0*zv.x; acc0.y += w0*zv.y; acc0.z += w0*zv.z; acc0.w += w0*zv.w;
            acc1.x += w1*zv.x; acc1.y += w1*zv.y; acc1.z += w1*zv.z; acc1.w += w1*zv.w;
        }
        float* pb = jh ? pB : pA;
        *reinterpret_cast<float4*>(&pb[h0*128 + l*4])     = acc0;
        *reinterpret_cast<float4*>(&pb[(h0+1)*128 + l*4]) = acc1;
    }
    __syncthreads();

    // combine halves + apply edge LN gamma/beta, write CTX
    {
        int o = t * 4;
        int h = o >> 7, d = o & 127;
        float4 a  = *reinterpret_cast<float4*>(&pA[o]);
        float4 b4 = *reinterpret_cast<float4*>(&pB[o]);
        float4 g  = *reinterpret_cast<const float4*>(&gz[d]);
        float4 bb = *reinterpret_cast<const float4*>(&bz[d]);
        float s0 = sh[h];
        float4 r4;
        r4.x = g.x*(a.x + b4.x - s0) + bb.x;
        r4.y = g.y*(a.y + b4.y - s0) + bb.y;
        r4.z = g.z*(a.z + b4.z - s0) + bb.z;
        r4.w = g.w*(a.w + b4.w - s0) + bb.w;
        *reinterpret_cast<float4*>(&g_CTX[(size_t)bi*1024 + o]) = r4;
    }
}

// ---------------- launch ----------------
extern "C" void kernel_launch(void* const* d_in, const int* in_sizes, int n_in,
                              void* d_out, int out_size) {
    const float* z    = (const float*)d_in[0];
    const float* s    = (const float*)d_in[1];
    const int*   mask = (const int*)d_in[2];
    const float* wq   = (const float*)d_in[3];
    const float* bq   = (const float*)d_in[4];
    const float* wk   = (const float*)d_in[5];
    const float* bk   = (const float*)d_in[6];
    const float* wv   = (const float*)d_in[7];
    const float* bv   = (const float*)d_in[8];
    const float* wo   = (const float*)d_in[9];
    const float* bo   = (const float*)d_in[10];
    const float* gz   = (const float*)d_in[11];
    const float* bz   = (const float*)d_in[12];
    const float* gs   = (const float*)d_in[13];
    const float* bs   = (const float*)d_in[14];
    float* out = (float*)d_out;

    const int attn_smem = ATTN_SMEM_FLOATS * (int)sizeof(float);
    cudaFuncSetAttribute(attn_kernel, cudaFuncAttributeMaxDynamicSharedMemorySize, attn_smem);

    float *SN, *Q, *QKG, *CTX, *OUTS, *Wk2;
    cudaGetSymbolAddress((void**)&SN,   g_SN);
    cudaGetSymbolAddress((void**)&Q,    g_Q);
    cudaGetSymbolAddress((void**)&QKG,  g_QKG);
    cudaGetSymbolAddress((void**)&CTX,  g_CTX);
    cudaGetSymbolAddress((void**)&OUTS, g_OUTS);
    cudaGetSymbolAddress((void**)&Wk2,  g_Wk2);

    // 1) layernorm s_query
    ln_s_kernel<<<BI, 256>>>(s, gs, bs);
    // 2) weight folds
    prep_wkb_kernel<<<1, 256>>>(wk, bk, bz);
    prep_wk2_kernel<<<128, 256>>>(wk, gz);
    // 3) Q = SN @ wq^T + bq   [2048,256] x [256,256]
    gemm_bt_kernel<<<dim3(DS/32, BI/128), 256>>>(SN, DS, wq, DS, bq, Q, DS, DS, DS, 0);
    // 4) per-head score constants
    cq_kernel<<<BI*Hh/256, 256>>>();
    // 5) QKG = Q(head-block) @ Wk2^T   [2048,1024], K=32 per head
    gemm_bt_kernel<<<dim3(Hh*DZ/32, BI/128), 256>>>(Q, DS, Wk2, HDIM, nullptr, QKG, Hh*DZ, HDIM, DZ, HDIM);
    // 6) fused edge-LN + attention -> CTX
    attn_kernel<<<BI, 256, attn_smem>>>(z, mask, gz, bz);
    // 7) OUTS = wv_h @ ctx_h + bv   (block-diagonal, K=128)
    gemm_bt_kernel<<<dim3(DS/32, BI/128), 256>>>(CTX, Hh*DZ, wv, DZ, bv, OUTS, DS, DZ, HDIM, DZ);
    // 8) FINAL = OUTS @ wo^T + bo -> d_out
    gemm_bt_kernel<<<dim3(DS/32, BI/128), 256>>>(OUTS, DS, wo, DS, bo, out, DS, DS, DS, 0);
}

// round 3
// speedup vs baseline: 1.1021x; 1.1021x over previous
#include <cuda_runtime.h>
#include <math.h>

// Problem constants
#define Bb 16
#define Nn 128
#define DZ 128
#define DS 256
#define Hh 8
#define HDIM 32
#define BI (Bb*Nn)               // 2048 (b,i) pairs
#define INV_SCALE 0.17677669529663687f   // 1/sqrt(32)
#define LN_EPS 1e-5f
#define ZP 132                   // padded z-tile row stride (floats)

// ---------------- scratch (no allocations allowed) ----------------
__device__ __align__(16) float g_SN  [BI*DS];
__device__ __align__(16) float g_Q   [BI*DS];
__device__ __align__(16) float g_QKG [BI*Hh*DZ];
__device__ __align__(16) float g_CQ  [BI*Hh];
__device__ __align__(16) float g_CTX [BI*Hh*DZ];
__device__ __align__(16) float g_OUTS[BI*DS];
__device__ __align__(16) float g_wkb [DS];
__device__ __align__(16) float g_Wk2 [Hh*DZ*HDIM];

// ---------------- s_query layernorm ----------------
__global__ void ln_s_kernel(const float* __restrict__ s, const float* __restrict__ gs,
                            const float* __restrict__ bs) {
    int bi = blockIdx.x;
    int t  = threadIdx.x;
    float x = s[(size_t)bi*DS + t];
    float sm = x, sq = x*x;
    #pragma unroll
    for (int o = 16; o > 0; o >>= 1) {
        sm += __shfl_xor_sync(0xffffffffu, sm, o);
        sq += __shfl_xor_sync(0xffffffffu, sq, o);
    }
    __shared__ float ps[8], pq[8], mv[2];
    int w = t >> 5, l = t & 31;
    if (l == 0) { ps[w] = sm; pq[w] = sq; }
    __syncthreads();
    if (t == 0) {
        float a = 0.f, b2 = 0.f;
        #pragma unroll
        for (int k = 0; k < 8; k++) { a += ps[k]; b2 += pq[k]; }
        float m = a * (1.0f/DS);
        mv[0] = m;
        mv[1] = rsqrtf(b2 * (1.0f/DS) - m*m + LN_EPS);
    }
    __syncthreads();
    g_SN[(size_t)bi*DS + t] = (x - mv[0]) * mv[1] * gs[t] + bs[t];
}

// ---------------- weight prep ----------------
__global__ void prep_wkb_kernel(const float* __restrict__ wk, const float* __restrict__ bk,
                                const float* __restrict__ bz) {
    int r = threadIdx.x;
    float acc = 0.f;
    for (int d = 0; d < DZ; d++) acc += wk[(size_t)r*DZ + d] * bz[d];
    g_wkb[r] = acc + bk[r];
}

__global__ void prep_wk2_kernel(const float* __restrict__ wk, const float* __restrict__ gz) {
    int idx = blockIdx.x * 256 + threadIdx.x;
    int o = idx >> 5, e = idx & 31;
    int h = o >> 7,  d = o & 127;
    g_Wk2[idx] = wk[(size_t)(h*HDIM + e)*DZ + d] * gz[d] * INV_SCALE;
}

__global__ void cq_kernel() {
    int idx = blockIdx.x * 256 + threadIdx.x;
    int bi = idx >> 3, h = idx & 7;
    float acc = 0.f;
    #pragma unroll
    for (int e = 0; e < HDIM; e++)
        acc += g_Q[(size_t)bi*DS + h*HDIM + e] * g_wkb[h*HDIM + e];
    g_CQ[idx] = acc * INV_SCALE;
}

// ---------------- tf32 tensor-core GEMM ----------------
// C[r,c] = sum_k A[r, abase+k]*B[c,k] + bias[c], abase = (c0/head_cols)*ahs
// CTA: 64(M) x 32(N) tile, 4 warps (warp w -> rows w*16..w*16+15), BK=32.
__device__ __forceinline__ unsigned f2tf(float x) {
    unsigned r;
    asm("cvt.rna.tf32.f32 %0, %1;" : "=r"(r) : "f"(x));
    return r;
}

__global__ __launch_bounds__(128) void gemm_tf32_kernel(
        const float* __restrict__ A, int lda,
        const float* __restrict__ B, int ldb,
        const float* __restrict__ bias,
        float* __restrict__ C, int ldc,
        int Kb, int head_cols, int ahs) {
    __shared__ float As[64*36];
    __shared__ float Bs[32*36];
    int t = threadIdx.x;
    int w = t >> 5, lane = t & 31;
    int r0 = blockIdx.y * 64, c0 = blockIdx.x * 32;
    int abase = (c0 / head_cols) * ahs;

    float acc[4][4];
    #pragma unroll
    for (int nf = 0; nf < 4; nf++)
        #pragma unroll
        for (int q = 0; q < 4; q++) acc[nf][q] = 0.f;

    int gr = lane >> 2;       // group row 0..7
    int gc = lane & 3;        // group col 0..3
    int mb = w * 16;

    for (int kc = 0; kc < Kb; kc += 32) {
        // load A tile 64x32: 512 float4 slots, 4 per thread
        #pragma unroll
        for (int i = 0; i < 4; i++) {
            int idx = t + i*128;
            int row = idx >> 3, k4 = idx & 7;
            float4 v = *reinterpret_cast<const float4*>(&A[(size_t)(r0+row)*lda + abase + kc + k4*4]);
            *reinterpret_cast<float4*>(&As[row*36 + k4*4]) = v;
        }
        // load B tile 32x32: 256 float4 slots, 2 per thread
        #pragma unroll
        for (int i = 0; i < 2; i++) {
            int idx = t + i*128;
            int row = idx >> 3, k4 = idx & 7;
            float4 v = *reinterpret_cast<const float4*>(&B[(size_t)(c0+row)*ldb + kc + k4*4]);
            *reinterpret_cast<float4*>(&Bs[row*36 + k4*4]) = v;
        }
        __syncthreads();
        #pragma unroll
        for (int kb = 0; kb < 4; kb++) {
            int ko = kb * 8;
            unsigned a0 = f2tf(As[(mb+gr)*36   + ko + gc]);
            unsigned a1 = f2tf(As[(mb+gr+8)*36 + ko + gc]);
            unsigned a2 = f2tf(As[(mb+gr)*36   + ko + gc + 4]);
            unsigned a3 = f2tf(As[(mb+gr+8)*36 + ko + gc + 4]);
            #pragma unroll
            for (int nf = 0; nf < 4; nf++) {
                unsigned b0 = f2tf(Bs[(nf*8+gr)*36 + ko + gc]);
                unsigned b1 = f2tf(Bs[(nf*8+gr)*36 + ko + gc + 4]);
                asm volatile(
                    "mma.sync.aligned.m16n8k8.row.col.f32.tf32.tf32.f32 "
                    "{%0,%1,%2,%3}, {%4,%5,%6,%7}, {%8,%9}, {%0,%1,%2,%3};"
                    : "+f"(acc[nf][0]), "+f"(acc[nf][1]), "+f"(acc[nf][2]), "+f"(acc[nf][3])
                    : "r"(a0), "r"(a1), "r"(a2), "r"(a3), "r"(b0), "r"(b1));
            }
        }
        __syncthreads();
    }

    // epilogue
    #pragma unroll
    for (int nf = 0; nf < 4; nf++) {
        int col = c0 + nf*8 + gc*2;
        float bx = 0.f, by = 0.f;
        if (bias) { bx = bias[col]; by = bias[col+1]; }
        int row = r0 + mb + gr;
        float2 v0 = make_float2(acc[nf][0] + bx, acc[nf][1] + by);
        float2 v1 = make_float2(acc[nf][2] + bx, acc[nf][3] + by);
        *reinterpret_cast<float2*>(&C[(size_t)row*ldc + col])     = v0;
        *reinterpret_cast<float2*>(&C[(size_t)(row+8)*ldc + col]) = v1;
    }
}

// ---------------- fused edge-LN + attention kernel (unchanged from R2 pass) ----------------
#define ATTN_SMEM_FLOATS (128*ZP + 1024*4 + 128*2 + 24)

__global__ void attn_kernel(const float* __restrict__ z, const int* __restrict__ mask,
                            const float* __restrict__ gz, const float* __restrict__ bz) {
    extern __shared__ float smem[];
    float* zt  = smem;
    float* qkg = zt  + 128*ZP;
    float* sc  = qkg + 1024;
    float* pA  = sc  + 1024;
    float* pB  = pA  + 1024;
    float* mj  = pB  + 1024;
    float* rj  = mj  + 128;
    float* Ah  = rj  + 128;
    float* cqh = Ah  + 8;
    float* sh  = cqh + 8;

    int bi = blockIdx.x;
    int b  = bi >> 7;
    int t  = threadIdx.x, w = t >> 5, l = t & 31;

    {
        float4 v = *reinterpret_cast<const float4*>(&g_QKG[(size_t)bi*1024 + t*4]);
        *reinterpret_cast<float4*>(&qkg[t*4]) = v;
    }
    if (t < 8) cqh[t] = g_CQ[(size_t)bi*8 + t];

    const float* zb = z + (size_t)bi * 128 * 128;
    for (int it = 0; it < 16; it++) {
        int j = w + it*8;
        float v0 = zb[j*128 + l];
        float v1 = zb[j*128 + l + 32];
        float v2 = zb[j*128 + l + 64];
        float v3 = zb[j*128 + l + 96];
        zt[j*ZP + l]      = v0;
        zt[j*ZP + l + 32] = v1;
        zt[j*ZP + l + 64] = v2;
        zt[j*ZP + l + 96] = v3;
        float s  = v0 + v1 + v2 + v3;
        float sq = v0*v0 + v1*v1 + v2*v2 + v3*v3;
        #pragma unroll
        for (int o = 16; o > 0; o >>= 1) {
            s  += __shfl_xor_sync(0xffffffffu, s,  o);
            sq += __shfl_xor_sync(0xffffffffu, sq, o);
        }
        if (l == 0) {
            float m = s * (1.0f/128.0f);
            mj[j] = m;
            rj[j] = rsqrtf(sq * (1.0f/128.0f) - m*m + LN_EPS);
        }
    }
    __syncthreads();

    {
        float4 v = *reinterpret_cast<float4*>(&qkg[w*128 + l*4]);
        float s = v.x + v.y + v.z + v.w;
        #pragma unroll
        for (int o = 16; o > 0; o >>= 1) s += __shfl_xor_sync(0xffffffffu, s, o);
        if (l == 0) Ah[w] = s;
    }
    __syncthreads();

    {
        int jb = t & 63;
        int h0 = (t >> 6) * 2;
        float a00 = 0.f, a01 = 0.f, a10 = 0.f, a11 = 0.f;
        #pragma unroll 8
        for (int d4 = 0; d4 < 32; d4++) {
            float4 q0 = *reinterpret_cast<float4*>(&qkg[h0*128 + d4*4]);
            float4 q1 = *reinterpret_cast<float4*>(&qkg[(h0+1)*128 + d4*4]);
            float4 zA = *reinterpret_cast<float4*>(&zt[jb*ZP + d4*4]);
            float4 zB = *reinterpret_cast<float4*>(&zt[(jb+64)*ZP + d4*4]);
            a00 += q0.x*zA.x + q0.y*zA.y + q0.z*zA.z + q0.w*zA.w;
            a01 += q0.x*zB.x + q0.y*zB.y + q0.z*zB.z + q0.w*zB.w;
            a10 += q1.x*zA.x + q1.y*zA.y + q1.z*zA.z + q1.w*zA.w;
            a11 += q1.x*zB.x + q1.y*zB.y + q1.z*zB.z + q1.w*zB.w;
        }
        int jA = jb, jB = jb + 64;
        bool okA = mask[b*128 + jA] != 0;
        bool okB = mask[b*128 + jB] != 0;
        float rA = rj[jA], rB = rj[jB], mA = mj[jA], mB = mj[jB];
        float A0 = Ah[h0], A1 = Ah[h0+1], C0 = cqh[h0], C1 = cqh[h0+1];
        float s00 = rA*(a00 - mA*A0) + C0;
        float s01 = rB*(a01 - mB*A0) + C0;
        float s10 = rA*(a10 - mA*A1) + C1;
        float s11 = rB*(a11 - mB*A1) + C1;
        sc[h0*128 + jA]     = okA ? s00 : -3.0e38f;
        sc[h0*128 + jB]     = okB ? s01 : -3.0e38f;
        sc[(h0+1)*128 + jA] = okA ? s10 : -3.0e38f;
        sc[(h0+1)*128 + jB] = okB ? s11 : -3.0e38f;
    }
    __syncthreads();

    {
        int h = w;
        float v0 = sc[h*128 + l],      v1 = sc[h*128 + l + 32];
        float v2 = sc[h*128 + l + 64], v3 = sc[h*128 + l + 96];
        float mx = fmaxf(fmaxf(v0, v1), fmaxf(v2, v3));
        #pragma unroll
        for (int o = 16; o > 0; o >>= 1) mx = fmaxf(mx, __shfl_xor_sync(0xffffffffu, mx, o));
        float e0 = expf(v0 - mx), e1 = expf(v1 - mx), e2 = expf(v2 - mx), e3 = expf(v3 - mx);
        float s = e0 + e1 + e2 + e3;
        #pragma unroll
        for (int o = 16; o > 0; o >>= 1) s += __shfl_xor_sync(0xffffffffu, s, o);
        float inv = 1.0f / s;
        float w0 = e0*inv*rj[l],      w1 = e1*inv*rj[l+32];
        float w2 = e2*inv*rj[l+64],   w3 = e3*inv*rj[l+96];
        sc[h*128 + l]      = w0;
        sc[h*128 + l + 32] = w1;
        sc[h*128 + l + 64] = w2;
        sc[h*128 + l + 96] = w3;
        float sm = w0*mj[l] + w1*mj[l+32] + w2*mj[l+64] + w3*mj[l+96];
        #pragma unroll
        for (int o = 16; o > 0; o >>= 1) sm += __shfl_xor_sync(0xffffffffu, sm, o);
        if (l == 0) sh[h] = sm;
    }
    __syncthreads();

    {
        int hp = w & 3, jh = w >> 2;
        int h0 = hp * 2;
        float4 acc0 = make_float4(0.f,0.f,0.f,0.f);
        float4 acc1 = make_float4(0.f,0.f,0.f,0.f);
        int j0 = jh * 64;
        #pragma unroll 4
        for (int jj = 0; jj < 64; jj++) {
            int j = j0 + jj;
            float w0 = sc[h0*128 + j];
            float w1 = sc[(h0+1)*128 + j];
            float4 zv = *reinterpret_cast<float4*>(&zt[j*ZP + l*4]);
            acc0.x += w0*zv.x; acc0.y += w0*zv.y; acc0.z += w0*zv.z; acc0.w += w0*zv.w;
            acc1.x += w1*zv.x; acc1.y += w1*zv.y; acc1.z += w1*zv.z; acc1.w += w1*zv.w;
        }
        float* pb = jh ? pB : pA;
        *reinterpret_cast<float4*>(&pb[h0*128 + l*4])     = acc0;
        *reinterpret_cast<float4*>(&pb[(h0+1)*128 + l*4]) = acc1;
    }
    __syncthreads();

    {
        int o = t * 4;
        int h = o >> 7, d = o & 127;
        float4 a  = *reinterpret_cast<float4*>(&pA[o]);
        float4 b4 = *reinterpret_cast<float4*>(&pB[o]);
        float4 g  = *reinterpret_cast<const float4*>(&gz[d]);
        float4 bb = *reinterpret_cast<const float4*>(&bz[d]);
        float s0 = sh[h];
        float4 r4;
        r4.x = g.x*(a.x + b4.x - s0) + bb.x;
        r4.y = g.y*(a.y + b4.y - s0) + bb.y;
        r4.z = g.z*(a.z + b4.z - s0) + bb.z;
        r4.w = g.w*(a.w + b4.w - s0) + bb.w;
        *reinterpret_cast<float4*>(&g_CTX[(size_t)bi*1024 + o]) = r4;
    }
}

// ---------------- launch ----------------
extern "C" void kernel_launch(void* const* d_in, const int* in_sizes, int n_in,
                              void* d_out, int out_size) {
    const float* z    = (const float*)d_in[0];
    const float* s    = (const float*)d_in[1];
    const int*   mask = (const int*)d_in[2];
    const float* wq   = (const float*)d_in[3];
    const float* bq   = (const float*)d_in[4];
    const float* wk   = (const float*)d_in[5];
    const float* bk   = (const float*)d_in[6];
    const float* wv   = (const float*)d_in[7];
    const float* bv   = (const float*)d_in[8];
    const float* wo   = (const float*)d_in[9];
    const float* bo   = (const float*)d_in[10];
    const float* gz   = (const float*)d_in[11];
    const float* bz   = (const float*)d_in[12];
    const float* gs   = (const float*)d_in[13];
    const float* bs   = (const float*)d_in[14];
    float* out = (float*)d_out;

    const int attn_smem = ATTN_SMEM_FLOATS * (int)sizeof(float);
    cudaFuncSetAttribute(attn_kernel, cudaFuncAttributeMaxDynamicSharedMemorySize, attn_smem);

    float *SN, *Q, *QKG, *CTX, *OUTS, *Wk2;
    cudaGetSymbolAddress((void**)&SN,   g_SN);
    cudaGetSymbolAddress((void**)&Q,    g_Q);
    cudaGetSymbolAddress((void**)&QKG,  g_QKG);
    cudaGetSymbolAddress((void**)&CTX,  g_CTX);
    cudaGetSymbolAddress((void**)&OUTS, g_OUTS);
    cudaGetSymbolAddress((void**)&Wk2,  g_Wk2);

    // 1) layernorm s_query
    ln_s_kernel<<<BI, 256>>>(s, gs, bs);
    // 2) weight folds
    prep_wkb_kernel<<<1, 256>>>(wk, bk, bz);
    prep_wk2_kernel<<<128, 256>>>(wk, gz);
    // 3) Q = SN @ wq^T + bq   [2048,256] K=256
    gemm_tf32_kernel<<<dim3(DS/32, BI/64), 128>>>(SN, DS, wq, DS, bq, Q, DS, DS, DS, 0);
    // 4) per-head score constants
    cq_kernel<<<BI*Hh/256, 256>>>();
    // 5) QKG = Q(head-block) @ Wk2^T   [2048,1024], K=32 per head
    gemm_tf32_kernel<<<dim3(Hh*DZ/32, BI/64), 128>>>(Q, DS, Wk2, HDIM, nullptr, QKG, Hh*DZ, HDIM, DZ, HDIM);
    // 6) fused edge-LN + attention -> CTX
    attn_kernel<<<BI, 256, attn_smem>>>(z, mask, gz, bz);
    // 7) OUTS = wv_h @ ctx_h + bv   (block-diagonal, K=128)
    gemm_tf32_kernel<<<dim3(DS/32, BI/64), 128>>>(CTX, Hh*DZ, wv, DZ, bv, OUTS, DS, DZ, HDIM, DZ);
    // 8) FINAL = OUTS @ wo^T + bo -> d_out
    gemm_tf32_kernel<<<dim3(DS/32, BI/64), 128>>>(OUTS, DS, wo, DS, bo, out, DS, DS, DS, 0);
}